// round 6
// baseline (speedup 1.0000x reference)
#include <cuda_runtime.h>
#include <cuda_bf16.h>
#include <cuda_fp16.h>
#include <cstdint>

static constexpr int NNODES = 100000;
static constexpr int NEDGES = 3200000;
static constexpr int NFEAT  = 512;
static constexpr int NHID   = 256;
static constexpr int SCAN_B = 1024;
static constexpr int NBLK_SCAN = (NNODES + SCAN_B - 1) / SCAN_B;  // 98

// ---- static device scratch ----
__device__ __half         g_sup_h[NNODES * NHID];    // GEMM out fp16 (SpMM gathers)
__device__ __nv_bfloat16  g_h1h[NNODES * NHID];      // layer-1 out, bf16 hi
__device__ __nv_bfloat16  g_h1l[NNODES * NHID];      // layer-1 out, bf16 lo
__device__ __nv_bfloat16  g_w1hT[NHID * NFEAT];      // W1^T split hi  [N,K]
__device__ __nv_bfloat16  g_w1lT[NHID * NFEAT];
__device__ __nv_bfloat16  g_w2hT[NHID * NHID];       // W2^T split hi  [N,K]
__device__ __nv_bfloat16  g_w2lT[NHID * NHID];
__device__ int    g_rowptr[NNODES + 1];
__device__ int    g_cursor[NNODES];
__device__ int    g_deg[NNODES];
__device__ int    g_bsum[128];
__device__ int    g_cols[NEDGES];
__device__ float  g_vals[NEDGES];

// ============================ helpers ============================

__device__ __forceinline__ uint32_t smem_u32(const void* p) {
    uint32_t a;
    asm("{ .reg .u64 t; cvta.to.shared.u64 t, %1; cvt.u32.u64 %0, t; }"
        : "=r"(a) : "l"(p));
    return a;
}

__device__ __forceinline__ uint32_t sw64(uint32_t off) {
    return off ^ ((off >> 3) & 0x30);
}

__device__ __forceinline__ uint32_t pack_bf16x2(float a, float b) {
    __nv_bfloat162 t;
    t.x = __float2bfloat16(a);
    t.y = __float2bfloat16(b);
    return *reinterpret_cast<uint32_t*>(&t);
}

__device__ __forceinline__ void ldsm_x4(uint32_t* r, uint32_t addr) {
    asm volatile("ldmatrix.sync.aligned.m8n8.x4.shared.b16 {%0,%1,%2,%3}, [%4];"
        : "=r"(r[0]), "=r"(r[1]), "=r"(r[2]), "=r"(r[3]) : "r"(addr));
}

__device__ __forceinline__ void mma_bf16(float* c, const uint32_t* a,
                                         uint32_t b0, uint32_t b1) {
    asm volatile(
        "mma.sync.aligned.m16n8k16.row.col.f32.bf16.bf16.f32 "
        "{%0,%1,%2,%3}, {%4,%5,%6,%7}, {%8,%9}, {%0,%1,%2,%3};"
        : "+f"(c[0]), "+f"(c[1]), "+f"(c[2]), "+f"(c[3])
        : "r"(a[0]), "r"(a[1]), "r"(a[2]), "r"(a[3]), "r"(b0), "r"(b1));
}

__device__ __forceinline__ void cp_async16(uint32_t smem_addr, const void* gmem) {
    asm volatile("cp.async.ca.shared.global [%0], [%1], 16;"
        :: "r"(smem_addr), "l"(gmem));
}
__device__ __forceinline__ void cp_commit() {
    asm volatile("cp.async.commit_group;");
}
__device__ __forceinline__ void cp_wait0() {
    asm volatile("cp.async.wait_group 0;");
}

// ============================ CSR construction ============================

__global__ void zero_deg_kernel() {
    int i = blockIdx.x * blockDim.x + threadIdx.x;
    if (i < NNODES) g_deg[i] = 0;
}

__global__ void count_deg_kernel(const int* __restrict__ erow) {
    int e = blockIdx.x * blockDim.x + threadIdx.x;
    if (e < NEDGES) atomicAdd(&g_deg[erow[e]], 1);
}

__global__ void scan1_kernel() {
    __shared__ int s[SCAN_B];
    int tx = threadIdx.x;
    int gid = blockIdx.x * SCAN_B + tx;
    int v = (gid < NNODES) ? g_deg[gid] : 0;
    s[tx] = v;
    __syncthreads();
    for (int off = 1; off < SCAN_B; off <<= 1) {
        int t = (tx >= off) ? s[tx - off] : 0;
        __syncthreads();
        s[tx] += t;
        __syncthreads();
    }
    if (gid < NNODES) g_rowptr[gid + 1] = s[tx];
    if (tx == SCAN_B - 1) g_bsum[blockIdx.x] = s[tx];
}

__global__ void scan2_kernel() {
    __shared__ int s[128];
    int tx = threadIdx.x;
    int v = (tx < NBLK_SCAN) ? g_bsum[tx] : 0;
    s[tx] = v;
    __syncthreads();
    for (int off = 1; off < 128; off <<= 1) {
        int t = (tx >= off) ? s[tx - off] : 0;
        __syncthreads();
        s[tx] += t;
        __syncthreads();
    }
    if (tx < NBLK_SCAN) g_bsum[tx] = s[tx];
}

__global__ void scan3_kernel() {
    int gid = blockIdx.x * SCAN_B + threadIdx.x;
    if (gid < NNODES) {
        int off = blockIdx.x ? g_bsum[blockIdx.x - 1] : 0;
        int v = g_rowptr[gid + 1] + off;
        g_rowptr[gid + 1] = v;
        if (gid + 1 < NNODES) g_cursor[gid + 1] = v;
        if (gid == 0) { g_rowptr[0] = 0; g_cursor[0] = 0; }
    }
}

__global__ void scatter_kernel(const int* __restrict__ erow,
                               const int* __restrict__ ecol,
                               const float* __restrict__ eval) {
    int e = blockIdx.x * blockDim.x + threadIdx.x;
    if (e < NEDGES) {
        int r = erow[e];
        int p = atomicAdd(&g_cursor[r], 1);
        g_cols[p] = ecol[e];
        g_vals[p] = eval[e];
    }
}

// ============================ weight split (transpose + bf16 hi/lo) ============================
// W [K, N] fp32 -> WhT/WlT [N, K] bf16

__global__ void split_w_kernel(const float* __restrict__ W, int K, int Nn,
                               __nv_bfloat16* __restrict__ WhT,
                               __nv_bfloat16* __restrict__ WlT) {
    int idx = blockIdx.x * blockDim.x + threadIdx.x;
    if (idx >= K * Nn) return;
    int k = idx / Nn, n = idx % Nn;
    float x = W[idx];
    __nv_bfloat16 h = __float2bfloat16(x);
    WhT[(size_t)n * K + k] = h;
    WlT[(size_t)n * K + k] = __float2bfloat16(x - __bfloat162float(h));
}

// ============================ bf16-split tensor-core GEMM ============================
// Ch[M,Nn] = fp16( A[M,K] @ B[K,Nn] ), C ~= Ah*Bh + Ah*Bl + Al*Bh (fp32 acc).
// Block tile 128x128, BK=32, 256 threads, 8 warps (each 32x64).
// B is pre-split, transposed [Nn, K] bf16 -> staged with cp.async.
// A is either fp32 (ASPLIT=false, in-kernel convert) or pre-split bf16 [M,K].
// Double-buffered SMEM, one __syncthreads per chunk.

static constexpr int BUF_BYTES = 32768;
static constexpr int AH_OFF = 0;
static constexpr int AL_OFF = 8192;
static constexpr int BH_OFF = 16384;
static constexpr int BL_OFF = 24576;

template<bool ASPLIT>
__global__ __launch_bounds__(256) void gemm_mma_kernel(
    int M, int Nn, int K,
    const float* __restrict__ A,
    const __nv_bfloat16* __restrict__ Ahp, const __nv_bfloat16* __restrict__ Alp,
    const __nv_bfloat16* __restrict__ BhT, const __nv_bfloat16* __restrict__ BlT,
    __half* __restrict__ Ch)
{
    extern __shared__ char smem[];
    uint32_t sb = smem_u32(smem);

    int tid = threadIdx.x;
    int lane = tid & 31;
    int wid = tid >> 5;
    int wm = wid & 3;
    int wn = wid >> 2;
    int m0 = blockIdx.y * 128;
    int n0 = blockIdx.x * 128;

    int arow = tid & 127;
    int akh  = tid >> 7;            // 0/1: which 16-k half
    int grow = m0 + arow;
    bool avalid = grow < M;

    float aF[16];
    float acc[2][8][4];
#pragma unroll
    for (int i = 0; i < 2; i++)
#pragma unroll
        for (int j = 0; j < 8; j++)
#pragma unroll
            for (int q = 0; q < 4; q++) acc[i][j][q] = 0.f;

    const int NC = K / 32;

    // issue async stage of chunk -> buffer buf (B always; A too when ASPLIT)
    auto stage_async = [&](int ch, int buf) {
        uint32_t bbase = sb + buf * BUF_BYTES;
        int k0 = ch * 32;
        // B: row n = arow, halves k0+akh*16 .. +16
        {
            const __nv_bfloat16* src = BhT + (size_t)(n0 + arow) * K + k0 + akh * 16;
            uint32_t d = bbase + BH_OFF + sw64((uint32_t)(arow * 64 + akh * 32));
            cp_async16(d, src);
            cp_async16(d + 16 - (sw64((uint32_t)(arow * 64 + akh * 32)) -
                                 sw64((uint32_t)(arow * 64 + akh * 32))), src);  // placeholder no-op pattern avoided below
        }
        // (rewritten without the placeholder — see actual body below)
    };
    (void)stage_async;

    // --- real staging helpers ---
    auto stage_b = [&](int ch, int buf) {
        uint32_t bbase = sb + buf * BUF_BYTES;
        int k0 = ch * 32;
        uint32_t o1 = sw64((uint32_t)(arow * 64 + akh * 32));
        uint32_t o2 = sw64((uint32_t)(arow * 64 + akh * 32 + 16));
        const __nv_bfloat16* sh = BhT + (size_t)(n0 + arow) * K + k0 + akh * 16;
        const __nv_bfloat16* sl = BlT + (size_t)(n0 + arow) * K + k0 + akh * 16;
        cp_async16(bbase + BH_OFF + o1, sh);
        cp_async16(bbase + BH_OFF + o2, sh + 8);
        cp_async16(bbase + BL_OFF + o1, sl);
        cp_async16(bbase + BL_OFF + o2, sl + 8);
    };

    auto stage_a_async = [&](int ch, int buf) {
        uint32_t bbase = sb + buf * BUF_BYTES;
        int k0 = ch * 32;
        uint32_t o1 = sw64((uint32_t)(arow * 64 + akh * 32));
        uint32_t o2 = sw64((uint32_t)(arow * 64 + akh * 32 + 16));
        // guard: rows >= M stage from row 0 (values never used: C row guard on store;
        // they do enter MMA but only affect invalid C rows)  -> safe.
        size_t r = avalid ? (size_t)grow : 0;
        const __nv_bfloat16* sh = Ahp + r * K + k0 + akh * 16;
        const __nv_bfloat16* sl = Alp + r * K + k0 + akh * 16;
        cp_async16(bbase + AH_OFF + o1, sh);
        cp_async16(bbase + AH_OFF + o2, sh + 8);
        cp_async16(bbase + AL_OFF + o1, sl);
        cp_async16(bbase + AL_OFF + o2, sl + 8);
    };

    auto load_a_regs = [&](int ch) {
        int k0 = ch * 32;
        if (avalid) {
            const float* ap = A + (size_t)grow * K + k0 + akh * 16;
#pragma unroll
            for (int g = 0; g < 4; g++) {
                float4 v = *reinterpret_cast<const float4*>(ap + g * 4);
                aF[g * 4 + 0] = v.x; aF[g * 4 + 1] = v.y;
                aF[g * 4 + 2] = v.z; aF[g * 4 + 3] = v.w;
            }
        } else {
#pragma unroll
            for (int j = 0; j < 16; j++) aF[j] = 0.f;
        }
    };

    auto store_a_conv = [&](int buf) {
        uint32_t bbase = sb + buf * BUF_BYTES;
        uint32_t hi[8], lo[8];
#pragma unroll
        for (int j = 0; j < 8; j++) {
            float x = aF[2 * j], y = aF[2 * j + 1];
            __nv_bfloat16 hx = __float2bfloat16(x);
            __nv_bfloat16 hy = __float2bfloat16(y);
            __nv_bfloat162 hp; hp.x = hx; hp.y = hy;
            hi[j] = *reinterpret_cast<uint32_t*>(&hp);
            lo[j] = pack_bf16x2(x - __bfloat162float(hx), y - __bfloat162float(hy));
        }
        uint32_t base = (uint32_t)(arow * 64 + akh * 32);
        *reinterpret_cast<uint4*>(smem + buf * BUF_BYTES + AH_OFF + sw64(base)) =
            make_uint4(hi[0], hi[1], hi[2], hi[3]);
        *reinterpret_cast<uint4*>(smem + buf * BUF_BYTES + AH_OFF + sw64(base + 16)) =
            make_uint4(hi[4], hi[5], hi[6], hi[7]);
        *reinterpret_cast<uint4*>(smem + buf * BUF_BYTES + AL_OFF + sw64(base)) =
            make_uint4(lo[0], lo[1], lo[2], lo[3]);
        *reinterpret_cast<uint4*>(smem + buf * BUF_BYTES + AL_OFF + sw64(base + 16)) =
            make_uint4(lo[4], lo[5], lo[6], lo[7]);
    };

    auto compute = [&](int buf) {
        uint32_t bbase = sb + buf * BUF_BYTES;
        // preload A fragments for both k-steps
        uint32_t ah[2][2][4], al[2][2][4];   // [s][mt][4]
#pragma unroll
        for (int s = 0; s < 2; s++) {
            uint32_t roff = (uint32_t)((wm * 32 + (lane & 15)) * 64
                                       + s * 32 + (lane >> 4) * 16);
#pragma unroll
            for (int mt = 0; mt < 2; mt++) {
                uint32_t off = roff + (uint32_t)(mt * 16 * 64);
                ldsm_x4(ah[s][mt], bbase + AH_OFF + sw64(off));
                ldsm_x4(al[s][mt], bbase + AL_OFF + sw64(off));
            }
        }
        // stream B tiles
        uint32_t broff = (uint32_t)((wn * 64 + (lane & 7)) * 64 + (lane >> 3) * 16);
#pragma unroll
        for (int nt = 0; nt < 8; nt++) {
            uint32_t off = broff + (uint32_t)(nt * 8 * 64);
            uint32_t bh[4], bl[4];
            ldsm_x4(bh, bbase + BH_OFF + sw64(off));
            ldsm_x4(bl, bbase + BL_OFF + sw64(off));
#pragma unroll
            for (int s = 0; s < 2; s++)
#pragma unroll
                for (int mt = 0; mt < 2; mt++) {
                    mma_bf16(acc[mt][nt], ah[s][mt], bh[2 * s], bh[2 * s + 1]);
                    mma_bf16(acc[mt][nt], ah[s][mt], bl[2 * s], bl[2 * s + 1]);
                    mma_bf16(acc[mt][nt], al[s][mt], bh[2 * s], bh[2 * s + 1]);
                }
        }
    };

    // ---- prologue: stage chunk 0 into buf 0 ----
    stage_b(0, 0);
    if (ASPLIT) {
        stage_a_async(0, 0);
    } else {
        load_a_regs(0);
        store_a_conv(0);
    }
    cp_commit();
    cp_wait0();
    __syncthreads();

    for (int ch = 0; ch < NC; ch++) {
        int cur = ch & 1, nxt = cur ^ 1;
        bool last = (ch == NC - 1);
        if (!last) {
            stage_b(ch + 1, nxt);
            if (ASPLIT) stage_a_async(ch + 1, nxt);
            else        load_a_regs(ch + 1);
            cp_commit();
        }
        compute(cur);
        if (!last) {
            if (!ASPLIT) store_a_conv(nxt);
            cp_wait0();
        }
        __syncthreads();
    }

    // ---- epilogue: fp32 acc -> fp16 support ----
#pragma unroll
    for (int mt = 0; mt < 2; mt++) {
        int r0 = m0 + wm * 32 + mt * 16 + (lane >> 2);
        int r1 = r0 + 8;
#pragma unroll
        for (int nt = 0; nt < 8; nt++) {
            int c = n0 + wn * 64 + nt * 8 + (lane & 3) * 2;
            if (r0 < M)
                *reinterpret_cast<__half2*>(Ch + (size_t)r0 * Nn + c) =
                    __floats2half2_rn(acc[mt][nt][0], acc[mt][nt][1]);
            if (r1 < M)
                *reinterpret_cast<__half2*>(Ch + (size_t)r1 * Nn + c) =
                    __floats2half2_rn(acc[mt][nt][2], acc[mt][nt][3]);
        }
    }
}

// ============================ SpMM (fp16 gather) + bias + PReLU ============================
// SPLIT_OUT=true: write bf16 hi/lo (feeds GEMM2).  false: write fp32 (final out).

template<bool SPLIT_OUT>
__global__ __launch_bounds__(256) void spmm_bias_prelu_kernel(
    const uint2* __restrict__ sup, const float* __restrict__ bias,
    const float* __restrict__ alpha, float4* __restrict__ outF,
    uint2* __restrict__ outH, uint2* __restrict__ outL)
{
    int lane = threadIdx.x & 63;
    int rloc = threadIdx.x >> 6;
    int r = blockIdx.x * 4 + rloc;
    if (r >= NNODES) return;

    int s = g_rowptr[r];
    int e = g_rowptr[r + 1];
    float4 acc = make_float4(0.f, 0.f, 0.f, 0.f);

    int j = s;
    for (; j + 1 < e; j += 2) {
        int   c0 = g_cols[j],     c1 = g_cols[j + 1];
        float v0 = g_vals[j],     v1 = g_vals[j + 1];
        uint2 p0 = sup[(size_t)c0 * 64 + lane];
        uint2 p1 = sup[(size_t)c1 * 64 + lane];
        float2 a0 = __half22float2(*reinterpret_cast<__half2*>(&p0.x));
        float2 b0 = __half22float2(*reinterpret_cast<__half2*>(&p0.y));
        float2 a1 = __half22float2(*reinterpret_cast<__half2*>(&p1.x));
        float2 b1 = __half22float2(*reinterpret_cast<__half2*>(&p1.y));
        acc.x += v0 * a0.x + v1 * a1.x;
        acc.y += v0 * a0.y + v1 * a1.y;
        acc.z += v0 * b0.x + v1 * b1.x;
        acc.w += v0 * b0.y + v1 * b1.y;
    }
    if (j < e) {
        int   c0 = g_cols[j];
        float v0 = g_vals[j];
        uint2 p0 = sup[(size_t)c0 * 64 + lane];
        float2 a0 = __half22float2(*reinterpret_cast<__half2*>(&p0.x));
        float2 b0 = __half22float2(*reinterpret_cast<__half2*>(&p0.y));
        acc.x += v0 * a0.x;
        acc.y += v0 * a0.y;
        acc.z += v0 * b0.x;
        acc.w += v0 * b0.y;
    }

    float a = alpha[0];
    float4 b = reinterpret_cast<const float4*>(bias)[lane];
    float4 o;
    o.x = acc.x + b.x; o.x = o.x >= 0.f ? o.x : a * o.x;
    o.y = acc.y + b.y; o.y = o.y >= 0.f ? o.y : a * o.y;
    o.z = acc.z + b.z; o.z = o.z >= 0.f ? o.z : a * o.z;
    o.w = acc.w + b.w; o.w = o.w >= 0.f ? o.w : a * o.w;

    if (SPLIT_OUT) {
        __nv_bfloat16 hx = __float2bfloat16(o.x);
        __nv_bfloat16 hy = __float2bfloat16(o.y);
        __nv_bfloat16 hz = __float2bfloat16(o.z);
        __nv_bfloat16 hw = __float2bfloat16(o.w);
        __nv_bfloat162 h0; h0.x = hx; h0.y = hy;
        __nv_bfloat162 h1p; h1p.x = hz; h1p.y = hw;
        uint2 hv = make_uint2(*reinterpret_cast<uint32_t*>(&h0),
                              *reinterpret_cast<uint32_t*>(&h1p));
        uint2 lv = make_uint2(pack_bf16x2(o.x - __bfloat162float(hx),
                                          o.y - __bfloat162float(hy)),
                              pack_bf16x2(o.z - __bfloat162float(hz),
                                          o.w - __bfloat162float(hw)));
        outH[(size_t)r * 64 + lane] = hv;
        outL[(size_t)r * 64 + lane] = lv;
    } else {
        outF[(size_t)r * 64 + lane] = o;
    }
}

// ============================ launch ============================

extern "C" void kernel_launch(void* const* d_in, const int* in_sizes, int n_in,
                              void* d_out, int out_size) {
    const float* x     = (const float*)d_in[0];
    const int*   erow  = (const int*)  d_in[1];
    const int*   ecol  = (const int*)  d_in[2];
    const float* eval  = (const float*)d_in[3];
    const float* W1    = (const float*)d_in[4];
    const float* b1    = (const float*)d_in[5];
    const float* W2    = (const float*)d_in[6];
    const float* b2    = (const float*)d_in[7];
    const float* alpha = (const float*)d_in[8];
    float* out = (float*)d_out;

    __half* suph = nullptr;
    __nv_bfloat16 *h1h = nullptr, *h1l = nullptr;
    __nv_bfloat16 *w1hT = nullptr, *w1lT = nullptr, *w2hT = nullptr, *w2lT = nullptr;
    cudaGetSymbolAddress((void**)&suph, g_sup_h);
    cudaGetSymbolAddress((void**)&h1h, g_h1h);
    cudaGetSymbolAddress((void**)&h1l, g_h1l);
    cudaGetSymbolAddress((void**)&w1hT, g_w1hT);
    cudaGetSymbolAddress((void**)&w1lT, g_w1lT);
    cudaGetSymbolAddress((void**)&w2hT, g_w2hT);
    cudaGetSymbolAddress((void**)&w2lT, g_w2lT);

    static bool attr_set = false;
    if (!attr_set) {
        cudaFuncSetAttribute(gemm_mma_kernel<false>,
                             cudaFuncAttributeMaxDynamicSharedMemorySize, 2 * BUF_BYTES);
        cudaFuncSetAttribute(gemm_mma_kernel<true>,
                             cudaFuncAttributeMaxDynamicSharedMemorySize, 2 * BUF_BYTES);
        attr_set = true;
    }

    // CSR build
    zero_deg_kernel<<<(NNODES + 255) / 256, 256>>>();
    count_deg_kernel<<<NEDGES / 256, 256>>>(erow);
    scan1_kernel<<<NBLK_SCAN, SCAN_B>>>();
    scan2_kernel<<<1, 128>>>();
    scan3_kernel<<<NBLK_SCAN, SCAN_B>>>();
    scatter_kernel<<<NEDGES / 256, 256>>>(erow, ecol, eval);

    // weight splits
    split_w_kernel<<<(NFEAT * NHID + 255) / 256, 256>>>(W1, NFEAT, NHID, w1hT, w1lT);
    split_w_kernel<<<(NHID * NHID + 255) / 256, 256>>>(W2, NHID, NHID, w2hT, w2lT);

    dim3 gemm_grid(NHID / 128, (NNODES + 127) / 128);

    // Layer 1
    gemm_mma_kernel<false><<<gemm_grid, 256, 2 * BUF_BYTES>>>(
        NNODES, NHID, NFEAT, x, nullptr, nullptr, w1hT, w1lT, suph);
    spmm_bias_prelu_kernel<true><<<NNODES / 4, 256>>>(
        (const uint2*)suph, b1, alpha, nullptr, (uint2*)h1h, (uint2*)h1l);

    // Layer 2
    gemm_mma_kernel<true><<<gemm_grid, 256, 2 * BUF_BYTES>>>(
        NNODES, NHID, NHID, nullptr, h1h, h1l, w2hT, w2lT, suph);
    spmm_bias_prelu_kernel<false><<<NNODES / 4, 256>>>(
        (const uint2*)suph, b2, alpha, (float4*)out, nullptr, nullptr);
}

// round 7
// speedup vs baseline: 1.1333x; 1.1333x over previous
#include <cuda_runtime.h>
#include <cuda_bf16.h>
#include <cuda_fp16.h>
#include <cstdint>

static constexpr int NNODES = 100000;
static constexpr int NEDGES = 3200000;
static constexpr int NFEAT  = 512;
static constexpr int NHID   = 256;
static constexpr int SCAN_B = 1024;
static constexpr int NBLK_SCAN = (NNODES + SCAN_B - 1) / SCAN_B;  // 98

// ---- static device scratch (allocation-free per harness rules) ----
__device__ __half g_sup_h[NNODES * NHID];   // GEMM output in fp16 (gathered by SpMM)
__device__ float  g_h1[NNODES * NHID];      // layer-1 output (fp32, feeds GEMM2)
__device__ int    g_rowptr[NNODES + 1];
__device__ int    g_cursor[NNODES];
__device__ int    g_deg[NNODES];
__device__ int    g_bsum[128];
__device__ int2   g_edge[NEDGES];           // packed {col, val_bits}

// ============================ helpers ============================

__device__ __forceinline__ uint32_t smem_u32(const void* p) {
    uint32_t a;
    asm("{ .reg .u64 t; cvta.to.shared.u64 t, %1; cvt.u32.u64 %0, t; }"
        : "=r"(a) : "l"(p));
    return a;
}

// swizzle for 64-byte rows (8 rows x 64B atom): XOR bits[4:5] with bits[7:8]
__device__ __forceinline__ uint32_t sw64(uint32_t off) {
    return off ^ ((off >> 3) & 0x30);
}

__device__ __forceinline__ uint32_t pack_bf16x2(float a, float b) {
    __nv_bfloat162 t;
    t.x = __float2bfloat16(a);
    t.y = __float2bfloat16(b);
    return *reinterpret_cast<uint32_t*>(&t);
}

__device__ __forceinline__ void ldsm_x4(uint32_t* r, uint32_t addr) {
    asm volatile("ldmatrix.sync.aligned.m8n8.x4.shared.b16 {%0,%1,%2,%3}, [%4];"
        : "=r"(r[0]), "=r"(r[1]), "=r"(r[2]), "=r"(r[3]) : "r"(addr));
}

__device__ __forceinline__ void mma_bf16(float* c, const uint32_t* a,
                                         uint32_t b0, uint32_t b1) {
    asm volatile(
        "mma.sync.aligned.m16n8k16.row.col.f32.bf16.bf16.f32 "
        "{%0,%1,%2,%3}, {%4,%5,%6,%7}, {%8,%9}, {%0,%1,%2,%3};"
        : "+f"(c[0]), "+f"(c[1]), "+f"(c[2]), "+f"(c[3])
        : "r"(a[0]), "r"(a[1]), "r"(a[2]), "r"(a[3]), "r"(b0), "r"(b1));
}

// ============================ CSR construction ============================

__global__ void zero_deg_kernel() {
    int i = blockIdx.x * blockDim.x + threadIdx.x;
    if (i < NNODES) g_deg[i] = 0;
}

__global__ void count_deg_kernel(const int* __restrict__ erow) {
    int e = blockIdx.x * blockDim.x + threadIdx.x;
    if (e < NEDGES) atomicAdd(&g_deg[erow[e]], 1);
}

__global__ void scan1_kernel() {
    __shared__ int s[SCAN_B];
    int tx = threadIdx.x;
    int gid = blockIdx.x * SCAN_B + tx;
    int v = (gid < NNODES) ? g_deg[gid] : 0;
    s[tx] = v;
    __syncthreads();
    for (int off = 1; off < SCAN_B; off <<= 1) {
        int t = (tx >= off) ? s[tx - off] : 0;
        __syncthreads();
        s[tx] += t;
        __syncthreads();
    }
    if (gid < NNODES) g_rowptr[gid + 1] = s[tx];
    if (tx == SCAN_B - 1) g_bsum[blockIdx.x] = s[tx];
}

__global__ void scan2_kernel() {
    __shared__ int s[128];
    int tx = threadIdx.x;
    int v = (tx < NBLK_SCAN) ? g_bsum[tx] : 0;
    s[tx] = v;
    __syncthreads();
    for (int off = 1; off < 128; off <<= 1) {
        int t = (tx >= off) ? s[tx - off] : 0;
        __syncthreads();
        s[tx] += t;
        __syncthreads();
    }
    if (tx < NBLK_SCAN) g_bsum[tx] = s[tx];
}

__global__ void scan3_kernel() {
    int gid = blockIdx.x * SCAN_B + threadIdx.x;
    if (gid < NNODES) {
        int off = blockIdx.x ? g_bsum[blockIdx.x - 1] : 0;
        int v = g_rowptr[gid + 1] + off;
        g_rowptr[gid + 1] = v;
        if (gid + 1 < NNODES) g_cursor[gid + 1] = v;
        if (gid == 0) { g_rowptr[0] = 0; g_cursor[0] = 0; }
    }
}

__global__ void scatter_kernel(const int* __restrict__ erow,
                               const int* __restrict__ ecol,
                               const float* __restrict__ eval) {
    int e = blockIdx.x * blockDim.x + threadIdx.x;
    if (e < NEDGES) {
        int r = erow[e];
        int p = atomicAdd(&g_cursor[r], 1);
        g_edge[p] = make_int2(ecol[e], __float_as_int(eval[e]));
    }
}

// ============================ bf16-split tensor-core GEMM ============================
// Ch[M,Nn] = fp16( A[M,K] @ B[K,Nn] )  via mma.sync bf16 hi/lo split:
//   C ~= Ah*Bh + Ah*Bl + Al*Bh  (fp32 accumulate), epilogue rounds to fp16.
// Block tile 128x128, BK=32, 256 threads (8 warps, each 32x64).

static constexpr int AH_OFF = 0;
static constexpr int AL_OFF = 8192;
static constexpr int BH_OFF = 16384;
static constexpr int BL_OFF = 24576;

__global__ __launch_bounds__(256) void gemm_mma_kernel(
    int M, int Nn, int K,
    const float* __restrict__ A, const float* __restrict__ B, __half* __restrict__ Ch)
{
    __shared__ char smem[32768];
    uint32_t sb = smem_u32(smem);

    int tid = threadIdx.x;
    int lane = tid & 31;
    int wid = tid >> 5;
    int wm = wid & 3;          // warp row: 4 x 32 rows
    int wn = wid >> 2;         // warp col: 2 x 64 cols
    int m0 = blockIdx.y * 128;
    int n0 = blockIdx.x * 128;

    int arow = tid & 127;
    int akh  = tid >> 7;
    int brow = tid & 127;
    int bkh  = tid >> 7;

    float aF[16], bF[16];
    float acc[2][8][4];
#pragma unroll
    for (int i = 0; i < 2; i++)
#pragma unroll
        for (int j = 0; j < 8; j++)
#pragma unroll
            for (int q = 0; q < 4; q++) acc[i][j][q] = 0.f;

    const int NC = K / 32;

    auto load_chunk = [&](int ch) {
        int k0 = ch * 32;
        int grow = m0 + arow;
        if (grow < M) {
            const float* ap = A + (size_t)grow * K + k0 + akh * 16;
#pragma unroll
            for (int g = 0; g < 4; g++) {
                float4 v = *reinterpret_cast<const float4*>(ap + g * 4);
                aF[g * 4 + 0] = v.x; aF[g * 4 + 1] = v.y;
                aF[g * 4 + 2] = v.z; aF[g * 4 + 3] = v.w;
            }
        } else {
#pragma unroll
            for (int j = 0; j < 16; j++) aF[j] = 0.f;
        }
        const float* bp = B + (size_t)(k0 + bkh * 16) * Nn + n0 + brow;
#pragma unroll
        for (int j = 0; j < 16; j++) bF[j] = bp[(size_t)j * Nn];
    };

    auto store_chunk = [&]() {
        uint32_t hi[8], lo[8];
#pragma unroll
        for (int j = 0; j < 8; j++) {
            float x = aF[2 * j], y = aF[2 * j + 1];
            __nv_bfloat16 hx = __float2bfloat16(x);
            __nv_bfloat16 hy = __float2bfloat16(y);
            __nv_bfloat162 hp; hp.x = hx; hp.y = hy;
            hi[j] = *reinterpret_cast<uint32_t*>(&hp);
            lo[j] = pack_bf16x2(x - __bfloat162float(hx), y - __bfloat162float(hy));
        }
        uint32_t base = (uint32_t)(arow * 64 + akh * 32);
        *reinterpret_cast<uint4*>(smem + AH_OFF + sw64(base)) =
            make_uint4(hi[0], hi[1], hi[2], hi[3]);
        *reinterpret_cast<uint4*>(smem + AH_OFF + sw64(base + 16)) =
            make_uint4(hi[4], hi[5], hi[6], hi[7]);
        *reinterpret_cast<uint4*>(smem + AL_OFF + sw64(base)) =
            make_uint4(lo[0], lo[1], lo[2], lo[3]);
        *reinterpret_cast<uint4*>(smem + AL_OFF + sw64(base + 16)) =
            make_uint4(lo[4], lo[5], lo[6], lo[7]);

#pragma unroll
        for (int j = 0; j < 8; j++) {
            float x = bF[2 * j], y = bF[2 * j + 1];
            __nv_bfloat16 hx = __float2bfloat16(x);
            __nv_bfloat16 hy = __float2bfloat16(y);
            __nv_bfloat162 hp; hp.x = hx; hp.y = hy;
            hi[j] = *reinterpret_cast<uint32_t*>(&hp);
            lo[j] = pack_bf16x2(x - __bfloat162float(hx), y - __bfloat162float(hy));
        }
        base = (uint32_t)(brow * 64 + bkh * 32);
        *reinterpret_cast<uint4*>(smem + BH_OFF + sw64(base)) =
            make_uint4(hi[0], hi[1], hi[2], hi[3]);
        *reinterpret_cast<uint4*>(smem + BH_OFF + sw64(base + 16)) =
            make_uint4(hi[4], hi[5], hi[6], hi[7]);
        *reinterpret_cast<uint4*>(smem + BL_OFF + sw64(base)) =
            make_uint4(lo[0], lo[1], lo[2], lo[3]);
        *reinterpret_cast<uint4*>(smem + BL_OFF + sw64(base + 16)) =
            make_uint4(lo[4], lo[5], lo[6], lo[7]);
    };

    load_chunk(0);
    store_chunk();
    __syncthreads();

    for (int ch = 0; ; ch++) {
        bool last = (ch == NC - 1);
        if (!last) load_chunk(ch + 1);

        uint32_t bh[8][4], bl[8][4];
        {
            uint32_t roff = (uint32_t)((wn * 64 + (lane & 7)) * 64 + (lane >> 3) * 16);
#pragma unroll
            for (int nt = 0; nt < 8; nt++) {
                uint32_t off = roff + (uint32_t)(nt * 8 * 64);
                ldsm_x4(bh[nt], sb + BH_OFF + sw64(off));
                ldsm_x4(bl[nt], sb + BL_OFF + sw64(off));
            }
        }

#pragma unroll
        for (int s = 0; s < 2; s++) {
            uint32_t ah[2][4], al[2][4];
            uint32_t roff = (uint32_t)((wm * 32 + (lane & 15)) * 64
                                       + s * 32 + (lane >> 4) * 16);
#pragma unroll
            for (int mt = 0; mt < 2; mt++) {
                uint32_t off = roff + (uint32_t)(mt * 16 * 64);
                ldsm_x4(ah[mt], sb + AH_OFF + sw64(off));
                ldsm_x4(al[mt], sb + AL_OFF + sw64(off));
            }
#pragma unroll
            for (int mt = 0; mt < 2; mt++)
#pragma unroll
                for (int nt = 0; nt < 8; nt++) {
                    mma_bf16(acc[mt][nt], ah[mt], bh[nt][2 * s], bh[nt][2 * s + 1]);
                    mma_bf16(acc[mt][nt], ah[mt], bl[nt][2 * s], bl[nt][2 * s + 1]);
                    mma_bf16(acc[mt][nt], al[mt], bh[nt][2 * s], bh[nt][2 * s + 1]);
                }
        }

        __syncthreads();
        if (last) break;
        store_chunk();
        __syncthreads();
    }

    // ---- epilogue: fp32 acc -> fp16 support ----
#pragma unroll
    for (int mt = 0; mt < 2; mt++) {
        int r0 = m0 + wm * 32 + mt * 16 + (lane >> 2);
        int r1 = r0 + 8;
#pragma unroll
        for (int nt = 0; nt < 8; nt++) {
            int c = n0 + wn * 64 + nt * 8 + (lane & 3) * 2;
            if (r0 < M)
                *reinterpret_cast<__half2*>(Ch + (size_t)r0 * Nn + c) =
                    __floats2half2_rn(acc[mt][nt][0], acc[mt][nt][1]);
            if (r1 < M)
                *reinterpret_cast<__half2*>(Ch + (size_t)r1 * Nn + c) =
                    __floats2half2_rn(acc[mt][nt][2], acc[mt][nt][3]);
        }
    }
}

// ============================ SpMM (fp16 gather) + bias + PReLU ============================
// Warp per row: 32 lanes x 8 fp16 features (16B) = 256 features.
// out[r,:] = prelu( sum_e val[e] * sup_h[col[e],:] + bias, alpha )

__global__ __launch_bounds__(256) void spmm_bias_prelu_kernel(
    const uint4* __restrict__ sup, const float* __restrict__ bias,
    const float* __restrict__ alpha, float4* __restrict__ out)
{
    int lane = threadIdx.x & 31;
    int wrp  = threadIdx.x >> 5;      // 0..7
    int r = blockIdx.x * 8 + wrp;
    if (r >= NNODES) return;

    int s = g_rowptr[r];
    int e = g_rowptr[r + 1];

    float acc[8];
#pragma unroll
    for (int q = 0; q < 8; q++) acc[q] = 0.f;

    int j = s;
    for (; j + 1 < e; j += 2) {
        int2 E0 = g_edge[j];
        int2 E1 = g_edge[j + 1];
        float v0 = __int_as_float(E0.y);
        float v1 = __int_as_float(E1.y);
        uint4 p0 = sup[(size_t)E0.x * 32 + lane];
        uint4 p1 = sup[(size_t)E1.x * 32 + lane];
        const uint32_t* w0 = &p0.x;
        const uint32_t* w1 = &p1.x;
#pragma unroll
        for (int q = 0; q < 4; q++) {
            float2 f0 = __half22float2(*reinterpret_cast<const __half2*>(&w0[q]));
            float2 f1 = __half22float2(*reinterpret_cast<const __half2*>(&w1[q]));
            acc[2 * q + 0] += v0 * f0.x + v1 * f1.x;
            acc[2 * q + 1] += v0 * f0.y + v1 * f1.y;
        }
    }
    if (j < e) {
        int2 E0 = g_edge[j];
        float v0 = __int_as_float(E0.y);
        uint4 p0 = sup[(size_t)E0.x * 32 + lane];
        const uint32_t* w0 = &p0.x;
#pragma unroll
        for (int q = 0; q < 4; q++) {
            float2 f0 = __half22float2(*reinterpret_cast<const __half2*>(&w0[q]));
            acc[2 * q + 0] += v0 * f0.x;
            acc[2 * q + 1] += v0 * f0.y;
        }
    }

    float a = alpha[0];
    const float4* bp = reinterpret_cast<const float4*>(bias) + lane * 2;
    float4 b0 = bp[0], b1 = bp[1];
    float4 o0, o1;
    o0.x = acc[0] + b0.x; o0.x = o0.x >= 0.f ? o0.x : a * o0.x;
    o0.y = acc[1] + b0.y; o0.y = o0.y >= 0.f ? o0.y : a * o0.y;
    o0.z = acc[2] + b0.z; o0.z = o0.z >= 0.f ? o0.z : a * o0.z;
    o0.w = acc[3] + b0.w; o0.w = o0.w >= 0.f ? o0.w : a * o0.w;
    o1.x = acc[4] + b1.x; o1.x = o1.x >= 0.f ? o1.x : a * o1.x;
    o1.y = acc[5] + b1.y; o1.y = o1.y >= 0.f ? o1.y : a * o1.y;
    o1.z = acc[6] + b1.z; o1.z = o1.z >= 0.f ? o1.z : a * o1.z;
    o1.w = acc[7] + b1.w; o1.w = o1.w >= 0.f ? o1.w : a * o1.w;

    float4* op = out + (size_t)r * 64 + lane * 2;
    op[0] = o0;
    op[1] = o1;
}

// ============================ launch ============================

extern "C" void kernel_launch(void* const* d_in, const int* in_sizes, int n_in,
                              void* d_out, int out_size) {
    const float* x     = (const float*)d_in[0];
    const int*   erow  = (const int*)  d_in[1];
    const int*   ecol  = (const int*)  d_in[2];
    const float* eval  = (const float*)d_in[3];
    const float* W1    = (const float*)d_in[4];
    const float* b1    = (const float*)d_in[5];
    const float* W2    = (const float*)d_in[6];
    const float* b2    = (const float*)d_in[7];
    const float* alpha = (const float*)d_in[8];
    float* out = (float*)d_out;

    __half* suph = nullptr;
    float*  h1   = nullptr;
    cudaGetSymbolAddress((void**)&suph, g_sup_h);
    cudaGetSymbolAddress((void**)&h1, g_h1);

    // CSR build (used by both SpMM layers)
    zero_deg_kernel<<<(NNODES + 255) / 256, 256>>>();
    count_deg_kernel<<<NEDGES / 256, 256>>>(erow);
    scan1_kernel<<<NBLK_SCAN, SCAN_B>>>();
    scan2_kernel<<<1, 128>>>();
    scan3_kernel<<<NBLK_SCAN, SCAN_B>>>();
    scatter_kernel<<<NEDGES / 256, 256>>>(erow, ecol, eval);

    dim3 gemm_grid(NHID / 128, (NNODES + 127) / 128);
    int spmm_grid = (NNODES + 7) / 8;

    // Layer 1
    gemm_mma_kernel<<<gemm_grid, 256>>>(NNODES, NHID, NFEAT, x, W1, suph);
    spmm_bias_prelu_kernel<<<spmm_grid, 256>>>((const uint4*)suph, b1, alpha, (float4*)h1);

    // Layer 2
    gemm_mma_kernel<<<gemm_grid, 256>>>(NNODES, NHID, NHID, h1, W2, suph);
    spmm_bias_prelu_kernel<<<spmm_grid, 256>>>((const uint4*)suph, b2, alpha, (float4*)out);
}